// round 1
// baseline (speedup 1.0000x reference)
#include <cuda_runtime.h>
#include <math.h>

#define BB 4
#define LQ 2048
#define LK 2048
#define DM 1024
#define NH 16
#define DK 64
#define NEGV -1000000000.0f

// Scratch for projected q/k/v: [B, LEN, H*DK] row-major. 32MB each.
__device__ float g_q[BB * LQ * NH * DK];
__device__ float g_k[BB * LK * NH * DK];
__device__ float g_v[BB * LK * NH * DK];

// ---------------------------------------------------------------------------
// C[m][n] = sum_k A[m][k] * W[n][k] (+ bias[n])
// A: [M,K] row-major, W: [N,K] row-major. 128x128 block, BK=8, 8x8 per thread.
// ---------------------------------------------------------------------------
__global__ __launch_bounds__(256) void sgemm_tn(
    const float* __restrict__ A, const float* __restrict__ W,
    const float* __restrict__ bias, float* __restrict__ C,
    int M, int N, int K)
{
    __shared__ float As[8][128];
    __shared__ float Ws[8][128];

    const int tid = threadIdx.x;
    const int tx = tid & 15;
    const int ty = tid >> 4;
    const int bm = blockIdx.y * 128;
    const int bn = blockIdx.x * 128;

    const int lrow = tid >> 1;         // 0..127
    const int lcol = (tid & 1) * 4;    // 0 or 4

    const float* Aptr = A + (size_t)(bm + lrow) * K + lcol;
    const float* Wptr = W + (size_t)(bn + lrow) * K + lcol;

    float acc[8][8] = {};

    for (int k0 = 0; k0 < K; k0 += 8) {
        float4 av = *(const float4*)(Aptr + k0);
        float4 wv = *(const float4*)(Wptr + k0);
        As[lcol + 0][lrow] = av.x; As[lcol + 1][lrow] = av.y;
        As[lcol + 2][lrow] = av.z; As[lcol + 3][lrow] = av.w;
        Ws[lcol + 0][lrow] = wv.x; Ws[lcol + 1][lrow] = wv.y;
        Ws[lcol + 2][lrow] = wv.z; Ws[lcol + 3][lrow] = wv.w;
        __syncthreads();

#pragma unroll
        for (int kk = 0; kk < 8; ++kk) {
            float a[8], b[8];
            *(float4*)&a[0] = *(const float4*)&As[kk][ty * 4];
            *(float4*)&a[4] = *(const float4*)&As[kk][64 + ty * 4];
            *(float4*)&b[0] = *(const float4*)&Ws[kk][tx * 4];
            *(float4*)&b[4] = *(const float4*)&Ws[kk][64 + tx * 4];
#pragma unroll
            for (int i = 0; i < 8; ++i)
#pragma unroll
                for (int j = 0; j < 8; ++j)
                    acc[i][j] += a[i] * b[j];
        }
        __syncthreads();
    }

#pragma unroll
    for (int i = 0; i < 8; ++i) {
        int m = bm + ((i < 4) ? (ty * 4 + i) : (64 + ty * 4 + (i - 4)));
#pragma unroll
        for (int j = 0; j < 8; ++j) {
            int n = bn + ((j < 4) ? (tx * 4 + j) : (64 + tx * 4 + (j - 4)));
            float val = acc[i][j];
            if (bias) val += bias[n];
            C[(size_t)m * N + n] = val;
        }
    }
}

// ---------------------------------------------------------------------------
// Flash-style attention, fp32. Block = 64 queries of one (b,h).
// Loops over K/V in tiles of 32 with online softmax.
// ---------------------------------------------------------------------------
__global__ __launch_bounds__(256) void attn_kernel(
    const float* __restrict__ q, const float* __restrict__ k,
    const float* __restrict__ v, const int* __restrict__ mask,
    float* __restrict__ out)
{
    __shared__ float q_s[64][65];   // [query][d]
    __shared__ float kT_s[64][33];  // [d][key]   (transposed K tile)
    __shared__ float v_s[32][65];   // [key][d]
    __shared__ float p_s[64][33];   // scores / probabilities
    __shared__ float m_s[64], l_s[64], a_s[64];
    __shared__ int   msk_s[32];

    const int tid = threadIdx.x;
    const int tx = tid & 15;
    const int ty = tid >> 4;
    const int b = blockIdx.z;
    const int h = blockIdx.y;
    const int q0 = blockIdx.x * 64;

    // Load Q tile (coalesced on d)
    for (int idx = tid; idx < 64 * 64; idx += 256) {
        int i = idx >> 6, d = idx & 63;
        q_s[i][d] = q[((size_t)(b * LQ + q0 + i) * NH + h) * DK + d];
    }
    if (tid < 64) { m_s[tid] = -INFINITY; l_s[tid] = 0.0f; }

    float o[4][4] = {};
    const float scale = 0.125f;  // 1/sqrt(64)

    for (int kt = 0; kt < LK; kt += 32) {
        __syncthreads();  // protect previous-iter p_s/v_s reads + first-iter q_s

        for (int idx = tid; idx < 32 * 64; idx += 256) {
            int j = idx >> 6, d = idx & 63;
            size_t gi = ((size_t)(b * LK + kt + j) * NH + h) * DK + d;
            kT_s[d][j] = k[gi];
            v_s[j][d]  = v[gi];
        }
        if (tid < 32) msk_s[tid] = mask[b * LK + kt + tid];
        __syncthreads();

        // S[64x32] = Q Kt; thread -> 4 rows x 2 cols
        float s[4][2] = {};
#pragma unroll 8
        for (int d = 0; d < 64; ++d) {
            float a0 = q_s[ty * 4 + 0][d];
            float a1 = q_s[ty * 4 + 1][d];
            float a2 = q_s[ty * 4 + 2][d];
            float a3 = q_s[ty * 4 + 3][d];
            float b0 = kT_s[d][tx * 2 + 0];
            float b1 = kT_s[d][tx * 2 + 1];
            s[0][0] += a0 * b0; s[0][1] += a0 * b1;
            s[1][0] += a1 * b0; s[1][1] += a1 * b1;
            s[2][0] += a2 * b0; s[2][1] += a2 * b1;
            s[3][0] += a3 * b0; s[3][1] += a3 * b1;
        }
#pragma unroll
        for (int ii = 0; ii < 4; ++ii)
#pragma unroll
            for (int jj = 0; jj < 2; ++jj) {
                float val = s[ii][jj] * scale;
                if (msk_s[tx * 2 + jj] == 0) val = NEGV;
                p_s[ty * 4 + ii][tx * 2 + jj] = val;
            }
        __syncthreads();

        // Online softmax per row (64 rows handled by threads 0..63)
        if (tid < 64) {
            const int r = tid;
            float mt = -INFINITY;
#pragma unroll
            for (int j = 0; j < 32; ++j) mt = fmaxf(mt, p_s[r][j]);
            float mn = fmaxf(m_s[r], mt);
            float al = __expf(m_s[r] - mn);
            float ls = 0.0f;
#pragma unroll
            for (int j = 0; j < 32; ++j) {
                float p = __expf(p_s[r][j] - mn);
                p_s[r][j] = p;
                ls += p;
            }
            l_s[r] = l_s[r] * al + ls;
            m_s[r] = mn;
            a_s[r] = al;
        }
        __syncthreads();

        // O = O*alpha + P @ V ; thread -> 4 rows x 4 d-cols
#pragma unroll
        for (int ii = 0; ii < 4; ++ii) {
            float al = a_s[ty * 4 + ii];
#pragma unroll
            for (int jj = 0; jj < 4; ++jj) o[ii][jj] *= al;
        }
#pragma unroll 8
        for (int kk = 0; kk < 32; ++kk) {
            float p0 = p_s[ty * 4 + 0][kk];
            float p1 = p_s[ty * 4 + 1][kk];
            float p2 = p_s[ty * 4 + 2][kk];
            float p3 = p_s[ty * 4 + 3][kk];
            float v0 = v_s[kk][tx * 4 + 0];
            float v1 = v_s[kk][tx * 4 + 1];
            float v2 = v_s[kk][tx * 4 + 2];
            float v3 = v_s[kk][tx * 4 + 3];
            o[0][0] += p0 * v0; o[0][1] += p0 * v1; o[0][2] += p0 * v2; o[0][3] += p0 * v3;
            o[1][0] += p1 * v0; o[1][1] += p1 * v1; o[1][2] += p1 * v2; o[1][3] += p1 * v3;
            o[2][0] += p2 * v0; o[2][1] += p2 * v1; o[2][2] += p2 * v2; o[2][3] += p2 * v3;
            o[3][0] += p3 * v0; o[3][1] += p3 * v1; o[3][2] += p3 * v2; o[3][3] += p3 * v3;
        }
    }
    __syncthreads();  // ensure final l_s visible to all

#pragma unroll
    for (int ii = 0; ii < 4; ++ii) {
        int i = ty * 4 + ii;
        float inv = 1.0f / l_s[i];
        size_t base = (size_t)(b * LQ + q0 + i) * (NH * DK) + h * DK;
#pragma unroll
        for (int jj = 0; jj < 4; ++jj)
            out[base + tx * 4 + jj] = o[ii][jj] * inv;
    }
}

// ---------------------------------------------------------------------------
extern "C" void kernel_launch(void* const* d_in, const int* in_sizes, int n_in,
                              void* d_out, int out_size)
{
    const float* Q    = (const float*)d_in[0];
    const float* K    = (const float*)d_in[1];
    const float* V    = (const float*)d_in[2];
    const int*   mask = (const int*)d_in[3];
    const float* Wq   = (const float*)d_in[4];
    const float* bq   = (const float*)d_in[5];
    const float* Wk   = (const float*)d_in[6];
    const float* Wv   = (const float*)d_in[7];
    const float* bv   = (const float*)d_in[8];
    float* out = (float*)d_out;

    float *qp, *kp, *vp;
    cudaGetSymbolAddress((void**)&qp, g_q);
    cudaGetSymbolAddress((void**)&kp, g_k);
    cudaGetSymbolAddress((void**)&vp, g_v);

    dim3 gproj((NH * DK) / 128, (BB * LQ) / 128);  // (8, 64)
    sgemm_tn<<<gproj, 256>>>(Q, Wq, bq,      qp, BB * LQ, NH * DK, DM);
    sgemm_tn<<<gproj, 256>>>(K, Wk, nullptr, kp, BB * LK, NH * DK, DM);
    sgemm_tn<<<gproj, 256>>>(V, Wv, bv,      vp, BB * LK, NH * DK, DM);

    dim3 gattn(LQ / 64, NH, BB);  // (32, 16, 4)
    attn_kernel<<<gattn, 256>>>(qp, kp, vp, mask, out);
}